// round 3
// baseline (speedup 1.0000x reference)
#include <cuda_runtime.h>

#define PATCH 7
#define PP (PATCH * PATCH)

// Scratch for MLP ping-pong (no cudaMalloc allowed). Sized for up to 2048 queries x 256 dim.
__device__ float g_buf0[2048 * 256];
__device__ float g_buf1[2048 * 256];

// ---------------------------------------------------------------------------
// MLP layer: Y[M,N] = act(X[M,K] @ W[K,N] + bias[N]),  act = ReLU or identity
// Block tile 64(M) x 32(N), BK=32, 256 threads, each thread a 2x4 micro-tile.
// Grid (M/64, N/32) = 16x8 = 128 blocks for M=1024,N=256 (~1 block/SM).
// X tile stored TRANSPOSED (XsT[k][m], stride 66) -> inner-k is one LDS.64 (a)
// + one LDS.128 (b) per 8 FFMA, conflict-free. Double-buffered smem with
// register-staged prefetch: ONE __syncthreads per K-tile (8 total).
// ---------------------------------------------------------------------------
template <bool RELU>
__global__ void __launch_bounds__(256) mlp_layer_kernel(
    const float* __restrict__ X, const float* __restrict__ W,
    const float* __restrict__ bias, float* __restrict__ Y,
    int M, int K, int N)
{
    __shared__ float XsT[2][32][66];   // [buf][k][m], stride 66 (even -> f2 align)
    __shared__ float Ws[2][32][32];    // [buf][k][n]

    const int tid = threadIdx.x;
    const int tx = tid & 7;            // 0..7  -> n-quad
    const int ty = tid >> 3;           // 0..31 -> m-pair

    const int bm = blockIdx.x * 64;
    const int bn = blockIdx.y * 32;

    float acc[2][4];
#pragma unroll
    for (int i = 0; i < 2; i++)
#pragma unroll
        for (int j = 0; j < 4; j++) acc[i][j] = 0.f;

    // Global-load index mapping
    const int xlm = tid >> 2;          // 0..63 : X row (m)
    const int xlk = (tid & 3) * 8;     // 0,8,16,24 : k-octet
    const int wlk = tid >> 3;          // 0..31 : W k row
    const int wln = (tid & 7) * 4;     // n-quad

    const int nTiles = K >> 5;         // K/32

    // Prologue: tile 0 straight to buffer 0
    {
        const float* xrow = &X[(size_t)(bm + xlm) * K + xlk];
        float4 x0 = *reinterpret_cast<const float4*>(xrow);
        float4 x1 = *reinterpret_cast<const float4*>(xrow + 4);
        XsT[0][xlk + 0][xlm] = x0.x; XsT[0][xlk + 1][xlm] = x0.y;
        XsT[0][xlk + 2][xlm] = x0.z; XsT[0][xlk + 3][xlm] = x0.w;
        XsT[0][xlk + 4][xlm] = x1.x; XsT[0][xlk + 5][xlm] = x1.y;
        XsT[0][xlk + 6][xlm] = x1.z; XsT[0][xlk + 7][xlm] = x1.w;
        float4 wv = *reinterpret_cast<const float4*>(&W[(size_t)wlk * N + bn + wln]);
        *reinterpret_cast<float4*>(&Ws[0][wlk][wln]) = wv;
    }
    __syncthreads();

    int cur = 0;
    for (int t = 0; t < nTiles; t++) {
        float4 px0, px1, pw;
        const bool more = (t + 1) < nTiles;
        if (more) {
            const int k0 = (t + 1) << 5;
            const float* xrow = &X[(size_t)(bm + xlm) * K + k0 + xlk];
            px0 = *reinterpret_cast<const float4*>(xrow);
            px1 = *reinterpret_cast<const float4*>(xrow + 4);
            pw  = *reinterpret_cast<const float4*>(&W[(size_t)(k0 + wlk) * N + bn + wln]);
        }

#pragma unroll
        for (int k = 0; k < 32; k++) {
            float4 bv = *reinterpret_cast<float4*>(&Ws[cur][k][tx * 4]);
            float2 av = *reinterpret_cast<float2*>(&XsT[cur][k][ty * 2]);
            acc[0][0] += av.x * bv.x; acc[0][1] += av.x * bv.y;
            acc[0][2] += av.x * bv.z; acc[0][3] += av.x * bv.w;
            acc[1][0] += av.y * bv.x; acc[1][1] += av.y * bv.y;
            acc[1][2] += av.y * bv.z; acc[1][3] += av.y * bv.w;
        }

        if (more) {
            const int nxt = cur ^ 1;
            XsT[nxt][xlk + 0][xlm] = px0.x; XsT[nxt][xlk + 1][xlm] = px0.y;
            XsT[nxt][xlk + 2][xlm] = px0.z; XsT[nxt][xlk + 3][xlm] = px0.w;
            XsT[nxt][xlk + 4][xlm] = px1.x; XsT[nxt][xlk + 5][xlm] = px1.y;
            XsT[nxt][xlk + 6][xlm] = px1.z; XsT[nxt][xlk + 7][xlm] = px1.w;
            *reinterpret_cast<float4*>(&Ws[nxt][wlk][wln]) = pw;
            __syncthreads();
            cur = nxt;
        }
    }

    float4 bb = *reinterpret_cast<const float4*>(&bias[bn + tx * 4]);
#pragma unroll
    for (int i = 0; i < 2; i++) {
        float4 v;
        v.x = acc[i][0] + bb.x;
        v.y = acc[i][1] + bb.y;
        v.z = acc[i][2] + bb.z;
        v.w = acc[i][3] + bb.w;
        if (RELU) {
            v.x = fmaxf(v.x, 0.f); v.y = fmaxf(v.y, 0.f);
            v.z = fmaxf(v.z, 0.f); v.w = fmaxf(v.w, 0.f);
        }
        *reinterpret_cast<float4*>(
            &Y[(size_t)(bm + ty * 2 + i) * N + bn + tx * 4]) = v;
    }
}

// ---------------------------------------------------------------------------
// Gather + dot + indices. One block per query, 256 threads (8 warps).
// Each warp handles patch pixels p = warp, warp+8, ... ; per pixel: contiguous
// 1KB feature row dotted with query embedding (in smem), warp-shuffle reduce.
// ---------------------------------------------------------------------------
__global__ void __launch_bounds__(256) gather_dot_kernel(
    const float* __restrict__ fmap,        // [B,H,W,D]
    const float* __restrict__ qe,          // [N,D]
    const float* __restrict__ qpos,        // [N,2] (x,y) normalized
    const int*   __restrict__ qoff,        // [B]
    const int*   __restrict__ shapes,      // [B,2]
    float* __restrict__ out_logits,        // [N,49]
    float* __restrict__ out_idx,           // [N,49,4] as float, may be null
    int B, int Q, int D)
{
    __shared__ float qe_s[512];
    __shared__ int meta[6]; // cy, cx, H, W, b, q_local

    const int q = blockIdx.x;
    const int tid = threadIdx.x;

    if (tid == 0) {
        int b = B - 1;
        while (b > 0 && q < qoff[b]) b--;
        int q_local = q - qoff[b];
        int Hs = shapes[2 * b + 0];
        int Ws = shapes[2 * b + 1];
        float px_f = qpos[2 * q + 0];
        float py_f = qpos[2 * q + 1];
        meta[0] = (int)(py_f * (float)Hs);   // truncation == astype(int32) for >=0
        meta[1] = (int)(px_f * (float)Ws);
        meta[2] = Hs;
        meta[3] = Ws;
        meta[4] = b;
        meta[5] = q_local;
    }
    for (int d = tid; d < D; d += blockDim.x) qe_s[d] = qe[(size_t)q * D + d];
    __syncthreads();

    const int cy = meta[0], cx = meta[1], H = meta[2], W = meta[3];
    const int b = meta[4], q_local = meta[5];
    const size_t base = (size_t)b * H * W * D;

    const int warp = tid >> 5;
    const int lane = tid & 31;
    const float4* qe4 = reinterpret_cast<const float4*>(qe_s);

    for (int p = warp; p < PP; p += 8) {
        const int i = p / PATCH;
        const int j = p % PATCH;
        int py = cy + i - PATCH / 2;
        int px = cx + j - PATCH / 2;
        py = min(max(py, 0), H - 1);
        px = min(max(px, 0), W - 1);

        const float4* row4 = reinterpret_cast<const float4*>(
            fmap + base + ((size_t)py * W + px) * D);

        float sum = 0.f;
        for (int d4 = lane; d4 * 4 < D; d4 += 32) {
            float4 f = row4[d4];
            float4 g = qe4[d4];
            sum += f.x * g.x + f.y * g.y + f.z * g.z + f.w * g.w;
        }
#pragma unroll
        for (int off = 16; off > 0; off >>= 1)
            sum += __shfl_down_sync(0xffffffffu, sum, off);

        if (lane == 0) out_logits[(size_t)q * PP + p] = sum;
        if (out_idx != nullptr && lane < 4) {
            int v = (lane == 0) ? b : (lane == 1) ? py : (lane == 2) ? px : q_local;
            out_idx[((size_t)q * PP + p) * 4 + lane] = (float)v;
        }
    }
}

// ---------------------------------------------------------------------------
extern "C" void kernel_launch(void* const* d_in, const int* in_sizes, int n_in,
                              void* d_out, int out_size)
{
    const float* fmap    = (const float*)d_in[0];
    const float* queries = (const float*)d_in[1];
    const float* qpos    = (const float*)d_in[2];
    const int*   qoff    = (const int*)d_in[3];
    const int*   shapes  = (const int*)d_in[4];
    const float* W0 = (const float*)d_in[5];
    const float* b0 = (const float*)d_in[6];
    const float* W1 = (const float*)d_in[7];
    const float* b1 = (const float*)d_in[8];
    const float* W2 = (const float*)d_in[9];
    const float* b2 = (const float*)d_in[10];
    const float* W3 = (const float*)d_in[11];
    const float* b3 = (const float*)d_in[12];

    const int D  = in_sizes[6];          // bias length
    const int Nq = in_sizes[1] / D;      // total queries
    const int B  = in_sizes[3];
    const int Q  = Nq / B;

    float* buf0 = nullptr;
    float* buf1 = nullptr;
    cudaGetSymbolAddress((void**)&buf0, g_buf0);
    cudaGetSymbolAddress((void**)&buf1, g_buf1);

    dim3 blk(256);
    dim3 grid(Nq / 64, D / 32);
    mlp_layer_kernel<true ><<<grid, blk>>>(queries, W0, b0, buf0, Nq, D, D);
    mlp_layer_kernel<true ><<<grid, blk>>>(buf0,    W1, b1, buf1, Nq, D, D);
    mlp_layer_kernel<true ><<<grid, blk>>>(buf1,    W2, b2, buf0, Nq, D, D);
    mlp_layer_kernel<false><<<grid, blk>>>(buf0,    W3, b3, buf1, Nq, D, D);

    float* logits = (float*)d_out;
    float* idxf = nullptr;
    if (out_size >= Nq * PP * 5) idxf = logits + (size_t)Nq * PP;

    gather_dot_kernel<<<Nq, 256>>>(fmap, buf1, qpos, qoff, shapes,
                                   logits, idxf, B, Q, D);
}